// round 15
// baseline (speedup 1.0000x reference)
#include <cuda_runtime.h>
#include <cuda_bf16.h>
#include <math.h>
#include <stdint.h>

#define BATCH 8
#define CH    512
#define CQD   64
#define NPIX  4096
#define KCAT  192   // [hi|lo|hi]·[hi|hi|lo] concat-K split-bf16 energy

// ---------------- scratch (device globals) ---------------------------------
__device__ __align__(256) __nv_bfloat16 g_attn_bf[(size_t)BATCH * NPIX * NPIX]; // 256MB exp(E)
__device__ __align__(256) __nv_bfloat16 g_xt_hi[(size_t)BATCH * NPIX * CH]; // 32 MB
__device__ __align__(256) __nv_bfloat16 g_xt_lo[(size_t)BATCH * NPIX * CH]; // 32 MB
__device__ __align__(256) __nv_bfloat16 g_v_bf[(size_t)BATCH * CH * NPIX];  // 32 MB
__device__ __align__(256) __nv_bfloat16 g_qcat[(size_t)BATCH * NPIX * KCAT];// 12 MB
__device__ __align__(256) __nv_bfloat16 g_kcat[(size_t)BATCH * NPIX * KCAT];// 12 MB
__device__ __align__(256) __nv_bfloat16 g_wv_bf[CH * CH];
__device__ __align__(256) __nv_bfloat16 g_wqk_hi[2 * CQD * CH];  // rows 0-63 Wq, 64-127 Wk
__device__ __align__(256) __nv_bfloat16 g_wqk_lo[2 * CQD * CH];
__device__ __align__(256) float g_rowsum[BATCH * NPIX];

// ---------------- helpers ---------------------------------------------------
__device__ __forceinline__ uint32_t smem_u32(const void* p) {
    uint32_t a;
    asm("{ .reg .u64 t; cvta.to.shared.u64 t, %1; cvt.u32.u64 %0, t; }" : "=r"(a) : "l"(p));
    return a;
}
__device__ __forceinline__ void cp16(uint32_t dst, const void* src) {
    asm volatile("cp.async.cg.shared.global [%0], [%1], 16;" :: "r"(dst), "l"(src));
}
#define CP_COMMIT() asm volatile("cp.async.commit_group;" ::: "memory")
#define CP_WAIT(n)  asm volatile("cp.async.wait_group %0;" :: "n"(n) : "memory")

__device__ __forceinline__ void ldm_x4(uint32_t* r, uint32_t addr) {
    asm volatile("ldmatrix.sync.aligned.m8n8.x4.shared.b16 {%0,%1,%2,%3}, [%4];"
                 : "=r"(r[0]), "=r"(r[1]), "=r"(r[2]), "=r"(r[3]) : "r"(addr));
}
__device__ __forceinline__ void mma_bf16(float* c, const uint32_t* a, const uint32_t* b) {
    asm volatile(
        "mma.sync.aligned.m16n8k16.row.col.f32.bf16.bf16.f32 "
        "{%0,%1,%2,%3}, {%4,%5,%6,%7}, {%8,%9}, {%0,%1,%2,%3};"
        : "+f"(c[0]), "+f"(c[1]), "+f"(c[2]), "+f"(c[3])
        : "r"(a[0]), "r"(a[1]), "r"(a[2]), "r"(a[3]), "r"(b[0]), "r"(b[1]));
}
// SW128 swizzle for 128B rows (BK=64 bf16): chunk 0..7 within row
__device__ __forceinline__ uint32_t sw8(uint32_t row, uint32_t ch) {
    return row * 128u + ((ch ^ (row & 7u)) << 4);
}

// ---------------- weight prep + rowsum zero ---------------------------------
__global__ __launch_bounds__(256) void prep_w(const float* __restrict__ Wv,
                                              const float* __restrict__ Wq,
                                              const float* __restrict__ Wk)
{
    int i = blockIdx.x * 256 + threadIdx.x;
    if (i < BATCH * NPIX) g_rowsum[i] = 0.f;
    if (i < CH * CH) {
        g_wv_bf[i] = __float2bfloat16(Wv[i]);
    } else {
        int j = i - CH * CH;
        if (j < 2 * CQD * CH) {
            float v = (j < CQD * CH) ? Wq[j] : Wk[j - CQD * CH];
            __nv_bfloat16 hi = __float2bfloat16(v);
            g_wqk_hi[j] = hi;
            g_wqk_lo[j] = __float2bfloat16(v - __bfloat162float(hi));
        }
    }
}

// ---------------- x transpose -> bf16 hi/lo [b][n][k] -----------------------
__global__ __launch_bounds__(256) void transpose_x(const float* __restrict__ x)
{
    __shared__ float t[32][33];
    int b = blockIdx.z;
    int n0 = blockIdx.x * 32, k0 = blockIdx.y * 32;
    int tx = threadIdx.x & 31, ty = threadIdx.x >> 5;
    #pragma unroll
    for (int i = 0; i < 32; i += 8)
        t[ty + i][tx] = x[(size_t)b * CH * NPIX + (size_t)(k0 + ty + i) * NPIX + n0 + tx];
    __syncthreads();
    #pragma unroll
    for (int i = 0; i < 32; i += 8) {
        float v = t[tx][ty + i];
        __nv_bfloat16 hi = __float2bfloat16(v);
        size_t idx = (size_t)b * NPIX * CH + (size_t)(n0 + ty + i) * CH + k0 + tx;
        g_xt_hi[idx] = hi;
        g_xt_lo[idx] = __float2bfloat16(v - __bfloat162float(hi));
    }
}

// ---------------- fused projections: vproj (y<4) + projqk (y>=4) ------------
// vproj tiles:  nT = x*128, mT = y*128        (128x128, K=512, 8 iters)
// projqk tiles: mT64 = ((y-4)*32 + x) * 64    (64x128,  K=3x512, 24 iters)
__global__ __launch_bounds__(256) void proj_fused(const float* __restrict__ bq,
                                                  const float* __restrict__ bk,
                                                  const float* __restrict__ bv)
{
    extern __shared__ __align__(1024) char smem[];
    uint32_t sb = smem_u32(smem);
    int tid = threadIdx.x, wid = tid >> 5, l = tid & 31;
    int b = blockIdx.z;

    if (blockIdx.y < 4) {
        // ================= vproj: v[c,n] = Wv[c,:]·x^T[n,:] + bv[c] =========
        constexpr int K = CH, KI = K / 64;   // 8
        constexpr int STG = 2 * 128 * 128;   // 32KB
        int warpM = wid >> 1, warpN = wid & 1;
        int nT = blockIdx.x * 128;
        int mT = blockIdx.y * 128;

        const __nv_bfloat16* Ag = g_wv_bf + (size_t)mT * CH;
        const __nv_bfloat16* Bg = g_xt_hi + (size_t)b * NPIX * CH + (size_t)nT * CH;

        auto load_stage = [&](int s, int kt) {
            uint32_t aB = sb + s * STG, bB = aB + 16384;
            int k0 = kt * 64;
            #pragma unroll
            for (int u = 0; u < 4; u++) {
                int idx = tid + u * 256, r = idx >> 3, c = idx & 7;
                cp16(aB + sw8(r, c), Ag + (size_t)r * K + k0 + c * 8);
            }
            #pragma unroll
            for (int u = 0; u < 4; u++) {
                int idx = tid + u * 256, r = idx >> 3, c = idx & 7;
                cp16(bB + sw8(r, c), Bg + (size_t)r * K + k0 + c * 8);
            }
            CP_COMMIT();
        };

        float acc[2][8][4];
        #pragma unroll
        for (int i = 0; i < 2; i++)
            #pragma unroll
            for (int j = 0; j < 8; j++)
                #pragma unroll
                for (int q = 0; q < 4; q++) acc[i][j][q] = 0.f;

        load_stage(0, 0); load_stage(1, 1);

        for (int it = 0; it < KI; it++) {
            int s = it % 3;
            if (it + 1 < KI) CP_WAIT(1); else CP_WAIT(0);
            __syncthreads();
            if (it + 2 < KI) load_stage((it + 2) % 3, it + 2);

            uint32_t aP = sb + s * STG, bP = aP + 16384;
            #pragma unroll
            for (int ks = 0; ks < 4; ks++) {
                uint32_t af[2][4];
                #pragma unroll
                for (int mi = 0; mi < 2; mi++) {
                    uint32_t row = warpM * 32 + mi * 16 + (l & 15);
                    uint32_t ch  = ks * 2 + (l >> 4);
                    ldm_x4(af[mi], aP + sw8(row, ch));
                }
                uint32_t bfm[4][4];
                #pragma unroll
                for (int nb = 0; nb < 4; nb++) {
                    uint32_t row = warpN * 64 + nb * 16 + ((l >> 4) << 3) + (l & 7);
                    uint32_t ch  = ks * 2 + ((l >> 3) & 1);
                    ldm_x4(bfm[nb], bP + sw8(row, ch));
                }
                #pragma unroll
                for (int mi = 0; mi < 2; mi++)
                    #pragma unroll
                    for (int ni = 0; ni < 8; ni++)
                        mma_bf16(acc[mi][ni], af[mi], &bfm[ni >> 1][(ni & 1) * 2]);
            }
            __syncthreads();
        }

        #pragma unroll
        for (int mi = 0; mi < 2; mi++)
            #pragma unroll
            for (int h = 0; h < 2; h++) {
                int m = mT + warpM * 32 + mi * 16 + h * 8 + (l >> 2);
                float bb = bv[m];
                #pragma unroll
                for (int ni = 0; ni < 8; ni++) {
                    int n = nT + warpN * 64 + ni * 8 + 2 * (l & 3);
                    __nv_bfloat162 pk = __floats2bfloat162_rn(acc[mi][ni][h * 2 + 0] + bb,
                                                              acc[mi][ni][h * 2 + 1] + bb);
                    *(__nv_bfloat162*)&g_v_bf[(size_t)b * CH * NPIX +
                                              (size_t)m * NPIX + n] = pk;
                }
            }
    } else {
        // ================= projqk: split-bf16 q/k projection =================
        constexpr int K = CH;
        constexpr int TOT_IT = 24;                     // 3 passes x 8
        constexpr int STG = 64 * 128 + 128 * 128;      // A 8KB + B 16KB
        int warpM = wid & 3, warpN = wid >> 2;
        int mT = ((blockIdx.y - 4) * 32 + blockIdx.x) * 64;

        const __nv_bfloat16* xh = g_xt_hi + (size_t)b * NPIX * CH + (size_t)mT * CH;
        const __nv_bfloat16* xl = g_xt_lo + (size_t)b * NPIX * CH + (size_t)mT * CH;

        auto load_stage = [&](int s, int gIt) {
            int pass = gIt >> 3;
            int k0 = (gIt & 7) * 64;
            const __nv_bfloat16* Ag = (pass == 1) ? xl : xh;
            const __nv_bfloat16* Bg = (pass == 2) ? g_wqk_lo : g_wqk_hi;
            uint32_t aB = sb + s * STG, bB = aB + 8192;
            #pragma unroll
            for (int u = 0; u < 2; u++) {
                int idx = tid + u * 256, r = idx >> 3, c = idx & 7;
                cp16(aB + sw8(r, c), Ag + (size_t)r * K + k0 + c * 8);
            }
            #pragma unroll
            for (int u = 0; u < 4; u++) {
                int idx = tid + u * 256, r = idx >> 3, c = idx & 7;
                cp16(bB + sw8(r, c), Bg + (size_t)r * K + k0 + c * 8);
            }
            CP_COMMIT();
        };

        float acc[8][4];
        #pragma unroll
        for (int j = 0; j < 8; j++)
            #pragma unroll
            for (int q = 0; q < 4; q++) acc[j][q] = 0.f;

        load_stage(0, 0); load_stage(1, 1);

        for (int it = 0; it < TOT_IT; it++) {
            int s = it % 3;
            if (it + 1 < TOT_IT) CP_WAIT(1); else CP_WAIT(0);
            __syncthreads();
            if (it + 2 < TOT_IT) load_stage((it + 2) % 3, it + 2);

            uint32_t aP = sb + s * STG, bP = aP + 8192;
            #pragma unroll
            for (int ks = 0; ks < 4; ks++) {
                uint32_t af[4];
                { uint32_t row = warpM * 16 + (l & 15), ch = ks * 2 + (l >> 4);
                  ldm_x4(af, aP + sw8(row, ch)); }
                uint32_t bfm[4][4];
                #pragma unroll
                for (int nb = 0; nb < 4; nb++) {
                    uint32_t row = warpN * 64 + nb * 16 + ((l >> 4) << 3) + (l & 7);
                    uint32_t ch  = ks * 2 + ((l >> 3) & 1);
                    ldm_x4(bfm[nb], bP + sw8(row, ch));
                }
                #pragma unroll
                for (int ni = 0; ni < 8; ni++)
                    mma_bf16(acc[ni], af, &bfm[ni >> 1][(ni & 1) * 2]);
            }
            __syncthreads();
        }

        const float* bias = (warpN == 0) ? bq : bk;
        __nv_bfloat16* dst = (warpN == 0) ? g_qcat : g_kcat;
        #pragma unroll
        for (int h = 0; h < 2; h++) {
            int n = mT + warpM * 16 + h * 8 + (l >> 2);
            size_t base = (size_t)b * NPIX * KCAT + (size_t)n * KCAT;
            #pragma unroll
            for (int ni = 0; ni < 8; ni++) {
                int cl = ni * 8 + 2 * (l & 3);
                float v0 = acc[ni][h * 2 + 0] + bias[cl];
                float v1 = acc[ni][h * 2 + 1] + bias[cl + 1];
                __nv_bfloat16 h0 = __float2bfloat16(v0);
                __nv_bfloat16 h1 = __float2bfloat16(v1);
                __nv_bfloat162 hi2; hi2.x = h0; hi2.y = h1;
                __nv_bfloat162 lo2;
                lo2.x = __float2bfloat16(v0 - __bfloat162float(h0));
                lo2.y = __float2bfloat16(v1 - __bfloat162float(h1));
                if (warpN == 0) {
                    *(__nv_bfloat162*)&dst[base + cl]       = hi2;
                    *(__nv_bfloat162*)&dst[base + 64 + cl]  = lo2;
                    *(__nv_bfloat162*)&dst[base + 128 + cl] = hi2;
                } else {
                    *(__nv_bfloat162*)&dst[base + cl]       = hi2;
                    *(__nv_bfloat162*)&dst[base + 64 + cl]  = hi2;
                    *(__nv_bfloat162*)&dst[base + 128 + cl] = lo2;
                }
            }
        }
    }
}

// ---------------- energy (256x128 tile, KI=3 fully prefetched) --------------
// P'[n,m] = exp(qcat[n,:]·kcat[m,:]); rowsum via atomics.
static constexpr int E_STG = 256 * 128 + 128 * 128;  // A 32KB + B 16KB
__global__ __launch_bounds__(256, 1) void energy_mma()
{
    constexpr int K = KCAT, KI = K / 64;   // 3
    extern __shared__ __align__(1024) char smem[];
    uint32_t sb = smem_u32(smem);

    int tid = threadIdx.x, wid = tid >> 5, l = tid & 31;
    int warpM = wid >> 1, warpN = wid & 1;
    int b = blockIdx.z;
    int nT = blockIdx.x * 128;   // m tile
    int mT = blockIdx.y * 256;   // n tile (256 rows)

    const __nv_bfloat16* Ag = g_qcat + (size_t)b * NPIX * KCAT + (size_t)mT * KCAT;
    const __nv_bfloat16* Bg = g_kcat + (size_t)b * NPIX * KCAT + (size_t)nT * KCAT;

    auto load_stage = [&](int s, int kt) {
        uint32_t aB = sb + s * E_STG, bB = aB + 32768;
        int k0 = kt * 64;
        #pragma unroll
        for (int u = 0; u < 8; u++) {
            int idx = tid + u * 256, r = idx >> 3, c = idx & 7;
            cp16(aB + sw8(r, c), Ag + (size_t)r * K + k0 + c * 8);
        }
        #pragma unroll
        for (int u = 0; u < 4; u++) {
            int idx = tid + u * 256, r = idx >> 3, c = idx & 7;
            cp16(bB + sw8(r, c), Bg + (size_t)r * K + k0 + c * 8);
        }
        CP_COMMIT();
    };

    float acc[4][8][4];
    #pragma unroll
    for (int i = 0; i < 4; i++)
        #pragma unroll
        for (int j = 0; j < 8; j++)
            #pragma unroll
            for (int q = 0; q < 4; q++) acc[i][j][q] = 0.f;

    load_stage(0, 0); load_stage(1, 1); load_stage(2, 2);

    #pragma unroll
    for (int it = 0; it < KI; it++) {
        if (it == 0) CP_WAIT(2);
        else if (it == 1) CP_WAIT(1);
        else CP_WAIT(0);
        __syncthreads();

        uint32_t aP = sb + it * E_STG, bP = aP + 32768;
        #pragma unroll
        for (int ks = 0; ks < 4; ks++) {
            uint32_t af[4][4];
            #pragma unroll
            for (int mi = 0; mi < 4; mi++) {
                uint32_t row = warpM * 64 + mi * 16 + (l & 15);
                uint32_t ch  = ks * 2 + (l >> 4);
                ldm_x4(af[mi], aP + sw8(row, ch));
            }
            uint32_t bfm[4][4];
            #pragma unroll
            for (int nb = 0; nb < 4; nb++) {
                uint32_t row = warpN * 64 + nb * 16 + ((l >> 4) << 3) + (l & 7);
                uint32_t ch  = ks * 2 + ((l >> 3) & 1);
                ldm_x4(bfm[nb], bP + sw8(row, ch));
            }
            #pragma unroll
            for (int mi = 0; mi < 4; mi++)
                #pragma unroll
                for (int ni = 0; ni < 8; ni++)
                    mma_bf16(acc[mi][ni], af[mi], &bfm[ni >> 1][(ni & 1) * 2]);
        }
        __syncthreads();
    }

    #pragma unroll
    for (int mi = 0; mi < 4; mi++)
        #pragma unroll
        for (int h = 0; h < 2; h++) {
            int n = mT + warpM * 64 + mi * 16 + h * 8 + (l >> 2);
            float rp = 0.f;
            #pragma unroll
            for (int ni = 0; ni < 8; ni++) {
                int m = nT + warpN * 64 + ni * 8 + 2 * (l & 3);
                float p0 = __expf(acc[mi][ni][h * 2 + 0]);
                float p1 = __expf(acc[mi][ni][h * 2 + 1]);
                rp += p0 + p1;
                *(__nv_bfloat162*)&g_attn_bf[(size_t)b * NPIX * NPIX +
                                             (size_t)n * NPIX + m] =
                    __floats2bfloat162_rn(p0, p1);
            }
            rp += __shfl_xor_sync(0xffffffffu, rp, 1);
            rp += __shfl_xor_sync(0xffffffffu, rp, 2);
            if ((l & 3) == 0)
                atomicAdd(&g_rowsum[b * NPIX + n], rp);
        }
}

// ---------------- out GEMM (BK=64, 4-stage): y = g*(v·P'^T)/rs + x ---------
static constexpr int OUT_STG = 256 * 128 + 128 * 128;  // A 32KB + B 16KB
__global__ __launch_bounds__(256, 1) void out_gemm(const float* __restrict__ xin,
                                                   const float* __restrict__ gamma,
                                                   float* __restrict__ y)
{
    constexpr int K = NPIX, KI = K / 64;   // 64
    extern __shared__ __align__(1024) char smem[];
    __shared__ float s_inv[128];
    uint32_t sb = smem_u32(smem);

    int tid = threadIdx.x, wid = tid >> 5, l = tid & 31;
    int warpM = wid >> 1, warpN = wid & 1;
    int b = blockIdx.z;
    int nT = blockIdx.x * 128;   // i tile
    int mT = blockIdx.y * 256;   // c tile

    if (tid < 128)
        s_inv[tid] = __fdividef(gamma[0], g_rowsum[b * NPIX + nT + tid]);

    const __nv_bfloat16* Ag = g_v_bf    + (size_t)b * CH * NPIX   + (size_t)mT * NPIX;
    const __nv_bfloat16* Bg = g_attn_bf + (size_t)b * NPIX * NPIX + (size_t)nT * NPIX;

    auto load_stage = [&](int s, int kt) {
        uint32_t aB = sb + s * OUT_STG, bB = aB + 32768;
        int k0 = kt * 64;
        #pragma unroll
        for (int u = 0; u < 8; u++) {
            int idx = tid + u * 256, r = idx >> 3, c = idx & 7;
            cp16(aB + sw8(r, c), Ag + (size_t)r * K + k0 + c * 8);
        }
        #pragma unroll
        for (int u = 0; u < 4; u++) {
            int idx = tid + u * 256, r = idx >> 3, c = idx & 7;
            cp16(bB + sw8(r, c), Bg + (size_t)r * K + k0 + c * 8);
        }
        CP_COMMIT();
    };

    float acc[4][8][4];
    #pragma unroll
    for (int i = 0; i < 4; i++)
        #pragma unroll
        for (int j = 0; j < 8; j++)
            #pragma unroll
            for (int q = 0; q < 4; q++) acc[i][j][q] = 0.f;

    load_stage(0, 0); load_stage(1, 1); load_stage(2, 2);

    for (int it = 0; it < KI; it++) {
        int s = it & 3;
        if (it + 1 < KI) CP_WAIT(2); else CP_WAIT(0);
        __syncthreads();
        if (it + 3 < KI) load_stage((it + 3) & 3, it + 3);

        uint32_t aP = sb + s * OUT_STG, bP = aP + 32768;
        #pragma unroll
        for (int ks = 0; ks < 4; ks++) {
            uint32_t af[4][4];
            #pragma unroll
            for (int mi = 0; mi < 4; mi++) {
                uint32_t row = warpM * 64 + mi * 16 + (l & 15);
                uint32_t ch  = ks * 2 + (l >> 4);
                ldm_x4(af[mi], aP + sw8(row, ch));
            }
            uint32_t bfm[4][4];
            #pragma unroll
            for (int nb = 0; nb < 4; nb++) {
                uint32_t row = warpN * 64 + nb * 16 + ((l >> 4) << 3) + (l & 7);
                uint32_t ch  = ks * 2 + ((l >> 3) & 1);
                ldm_x4(bfm[nb], bP + sw8(row, ch));
            }
            #pragma unroll
            for (int mi = 0; mi < 4; mi++)
                #pragma unroll
                for (int ni = 0; ni < 8; ni++)
                    mma_bf16(acc[mi][ni], af[mi], &bfm[ni >> 1][(ni & 1) * 2]);
        }
        __syncthreads();
    }

    #pragma unroll
    for (int mi = 0; mi < 4; mi++)
        #pragma unroll
        for (int h = 0; h < 2; h++) {
            int m = mT + warpM * 64 + mi * 16 + h * 8 + (l >> 2);
            #pragma unroll
            for (int ni = 0; ni < 8; ni++) {
                int nl = warpN * 64 + ni * 8 + 2 * (l & 3);
                int n = nT + nl;
                float i0 = s_inv[nl];
                float i1 = s_inv[nl + 1];
                size_t idx = (size_t)b * CH * NPIX + (size_t)m * NPIX + n;
                float2 xv = *(const float2*)(xin + idx);
                float2 o  = make_float2(fmaf(i0, acc[mi][ni][h * 2 + 0], xv.x),
                                        fmaf(i1, acc[mi][ni][h * 2 + 1], xv.y));
                *(float2*)(y + idx) = o;
            }
        }
}

// ---------------------------------------------------------------------------
extern "C" void kernel_launch(void* const* d_in, const int* in_sizes, int n_in,
                              void* d_out, int out_size)
{
    const float* x     = (const float*)d_in[0];
    const float* Wq    = (const float*)d_in[1];
    const float* bq    = (const float*)d_in[2];
    const float* Wk    = (const float*)d_in[3];
    const float* bk    = (const float*)d_in[4];
    const float* Wv    = (const float*)d_in[5];
    const float* bv    = (const float*)d_in[6];
    const float* gamma = (const float*)d_in[7];
    float* y = (float*)d_out;

    constexpr int PF_SMEM  = 3 * (2 * 128 * 128);          // 96 KB (max of paths)
    constexpr int E_SMEM   = 3 * E_STG;                    // 144 KB
    constexpr int OUT_SMEM = 4 * OUT_STG;                  // 192 KB

    cudaFuncSetAttribute(proj_fused, cudaFuncAttributeMaxDynamicSharedMemorySize, PF_SMEM);
    cudaFuncSetAttribute(energy_mma, cudaFuncAttributeMaxDynamicSharedMemorySize, E_SMEM);
    cudaFuncSetAttribute(out_gemm,   cudaFuncAttributeMaxDynamicSharedMemorySize, OUT_SMEM);

    prep_w<<<(CH * CH + 2 * CQD * CH + 255) / 256, 256>>>(Wv, Wq, Wk);
    transpose_x<<<dim3(NPIX / 32, CH / 32, BATCH), 256>>>(x);
    // fused: y<4 -> vproj (32x4 tiles), y in [4,6) -> projqk (64 tiles of 64 rows)
    proj_fused<<<dim3(32, 6, BATCH), 256, PF_SMEM>>>(bq, bk, bv);
    energy_mma<<<dim3(NPIX / 128, NPIX / 256, BATCH), 256, E_SMEM>>>();
    out_gemm<<<dim3(NPIX / 128, CH / 256, BATCH), 256, OUT_SMEM>>>(x, gamma, y);
}

// round 16
// speedup vs baseline: 1.0599x; 1.0599x over previous
#include <cuda_runtime.h>
#include <cuda_bf16.h>
#include <math.h>
#include <stdint.h>

#define BATCH 8
#define CH    512
#define CQD   64
#define NPIX  4096
#define KCAT  192   // [hi|lo|hi]·[hi|hi|lo] concat-K split-bf16 energy

// ---------------- scratch (device globals) ---------------------------------
__device__ __align__(256) __nv_bfloat16 g_attn_bf[(size_t)BATCH * NPIX * NPIX]; // 256MB exp(E)
__device__ __align__(256) __nv_bfloat16 g_xt_hi[(size_t)BATCH * NPIX * CH]; // 32 MB
__device__ __align__(256) __nv_bfloat16 g_xt_lo[(size_t)BATCH * NPIX * CH]; // 32 MB
__device__ __align__(256) __nv_bfloat16 g_v_bf[(size_t)BATCH * CH * NPIX];  // 32 MB
__device__ __align__(256) __nv_bfloat16 g_qcat[(size_t)BATCH * NPIX * KCAT];// 12 MB
__device__ __align__(256) __nv_bfloat16 g_kcat[(size_t)BATCH * NPIX * KCAT];// 12 MB
__device__ __align__(256) __nv_bfloat16 g_wv_bf[CH * CH];
__device__ __align__(256) __nv_bfloat16 g_wqk_hi[2 * CQD * CH];  // rows 0-63 Wq, 64-127 Wk
__device__ __align__(256) __nv_bfloat16 g_wqk_lo[2 * CQD * CH];
__device__ __align__(256) float g_rowsum[BATCH * NPIX];

// ---------------- helpers ---------------------------------------------------
__device__ __forceinline__ uint32_t smem_u32(const void* p) {
    uint32_t a;
    asm("{ .reg .u64 t; cvta.to.shared.u64 t, %1; cvt.u32.u64 %0, t; }" : "=r"(a) : "l"(p));
    return a;
}
__device__ __forceinline__ void cp16(uint32_t dst, const void* src) {
    asm volatile("cp.async.cg.shared.global [%0], [%1], 16;" :: "r"(dst), "l"(src));
}
#define CP_COMMIT() asm volatile("cp.async.commit_group;" ::: "memory")
#define CP_WAIT(n)  asm volatile("cp.async.wait_group %0;" :: "n"(n) : "memory")

__device__ __forceinline__ void ldm_x4(uint32_t* r, uint32_t addr) {
    asm volatile("ldmatrix.sync.aligned.m8n8.x4.shared.b16 {%0,%1,%2,%3}, [%4];"
                 : "=r"(r[0]), "=r"(r[1]), "=r"(r[2]), "=r"(r[3]) : "r"(addr));
}
__device__ __forceinline__ void mma_bf16(float* c, const uint32_t* a, const uint32_t* b) {
    asm volatile(
        "mma.sync.aligned.m16n8k16.row.col.f32.bf16.bf16.f32 "
        "{%0,%1,%2,%3}, {%4,%5,%6,%7}, {%8,%9}, {%0,%1,%2,%3};"
        : "+f"(c[0]), "+f"(c[1]), "+f"(c[2]), "+f"(c[3])
        : "r"(a[0]), "r"(a[1]), "r"(a[2]), "r"(a[3]), "r"(b[0]), "r"(b[1]));
}
// SW128 swizzle for 128B rows (BK=64 bf16): chunk 0..7 within row
__device__ __forceinline__ uint32_t sw8(uint32_t row, uint32_t ch) {
    return row * 128u + ((ch ^ (row & 7u)) << 4);
}

// ---------------- weight prep + rowsum zero ---------------------------------
__global__ __launch_bounds__(256) void prep_w(const float* __restrict__ Wv,
                                              const float* __restrict__ Wq,
                                              const float* __restrict__ Wk)
{
    int i = blockIdx.x * 256 + threadIdx.x;
    if (i < BATCH * NPIX) g_rowsum[i] = 0.f;
    if (i < CH * CH) {
        g_wv_bf[i] = __float2bfloat16(Wv[i]);
    } else {
        int j = i - CH * CH;
        if (j < 2 * CQD * CH) {
            float v = (j < CQD * CH) ? Wq[j] : Wk[j - CQD * CH];
            __nv_bfloat16 hi = __float2bfloat16(v);
            g_wqk_hi[j] = hi;
            g_wqk_lo[j] = __float2bfloat16(v - __bfloat162float(hi));
        }
    }
}

// ---------------- x transpose -> bf16 hi/lo [b][n][k] -----------------------
__global__ __launch_bounds__(256) void transpose_x(const float* __restrict__ x)
{
    __shared__ float t[32][33];
    int b = blockIdx.z;
    int n0 = blockIdx.x * 32, k0 = blockIdx.y * 32;
    int tx = threadIdx.x & 31, ty = threadIdx.x >> 5;
    #pragma unroll
    for (int i = 0; i < 32; i += 8)
        t[ty + i][tx] = x[(size_t)b * CH * NPIX + (size_t)(k0 + ty + i) * NPIX + n0 + tx];
    __syncthreads();
    #pragma unroll
    for (int i = 0; i < 32; i += 8) {
        float v = t[tx][ty + i];
        __nv_bfloat16 hi = __float2bfloat16(v);
        size_t idx = (size_t)b * NPIX * CH + (size_t)(n0 + ty + i) * CH + k0 + tx;
        g_xt_hi[idx] = hi;
        g_xt_lo[idx] = __float2bfloat16(v - __bfloat162float(hi));
    }
}

// ---------------- q/k projection via split-bf16 MMA (BK=64, 3-stage) --------
__global__ __launch_bounds__(256) void projqk_mma(const float* __restrict__ bq,
                                                  const float* __restrict__ bk)
{
    constexpr int K = CH;
    constexpr int TOT_IT = 24;                     // 3 passes x 8
    constexpr int STG = 64 * 128 + 128 * 128;      // A 8KB + B 16KB
    extern __shared__ __align__(1024) char smem[];
    uint32_t sb = smem_u32(smem);

    int tid = threadIdx.x, wid = tid >> 5, l = tid & 31;
    int warpM = wid & 3, warpN = wid >> 2;
    int b = blockIdx.z;
    int mT = blockIdx.y * 64;

    const __nv_bfloat16* xh = g_xt_hi + (size_t)b * NPIX * CH + (size_t)mT * CH;
    const __nv_bfloat16* xl = g_xt_lo + (size_t)b * NPIX * CH + (size_t)mT * CH;

    auto load_stage = [&](int s, int gIt) {
        int pass = gIt >> 3;
        int k0 = (gIt & 7) * 64;
        const __nv_bfloat16* Ag = (pass == 1) ? xl : xh;
        const __nv_bfloat16* Bg = (pass == 2) ? g_wqk_lo : g_wqk_hi;
        uint32_t aB = sb + s * STG, bB = aB + 8192;
        #pragma unroll
        for (int u = 0; u < 2; u++) {
            int idx = tid + u * 256, r = idx >> 3, c = idx & 7;
            cp16(aB + sw8(r, c), Ag + (size_t)r * K + k0 + c * 8);
        }
        #pragma unroll
        for (int u = 0; u < 4; u++) {
            int idx = tid + u * 256, r = idx >> 3, c = idx & 7;
            cp16(bB + sw8(r, c), Bg + (size_t)r * K + k0 + c * 8);
        }
        CP_COMMIT();
    };

    float acc[8][4];
    #pragma unroll
    for (int j = 0; j < 8; j++)
        #pragma unroll
        for (int q = 0; q < 4; q++) acc[j][q] = 0.f;

    load_stage(0, 0); load_stage(1, 1);

    for (int it = 0; it < TOT_IT; it++) {
        int s = it % 3;
        if (it + 1 < TOT_IT) CP_WAIT(1); else CP_WAIT(0);
        __syncthreads();
        if (it + 2 < TOT_IT) load_stage((it + 2) % 3, it + 2);

        uint32_t aP = sb + s * STG, bP = aP + 8192;
        #pragma unroll
        for (int ks = 0; ks < 4; ks++) {
            uint32_t af[4];
            { uint32_t row = warpM * 16 + (l & 15), ch = ks * 2 + (l >> 4);
              ldm_x4(af, aP + sw8(row, ch)); }
            uint32_t bfm[4][4];
            #pragma unroll
            for (int nb = 0; nb < 4; nb++) {
                uint32_t row = warpN * 64 + nb * 16 + ((l >> 4) << 3) + (l & 7);
                uint32_t ch  = ks * 2 + ((l >> 3) & 1);
                ldm_x4(bfm[nb], bP + sw8(row, ch));
            }
            #pragma unroll
            for (int ni = 0; ni < 8; ni++)
                mma_bf16(acc[ni], af, &bfm[ni >> 1][(ni & 1) * 2]);
        }
        __syncthreads();
    }

    const float* bias = (warpN == 0) ? bq : bk;
    __nv_bfloat16* dst = (warpN == 0) ? g_qcat : g_kcat;
    #pragma unroll
    for (int h = 0; h < 2; h++) {
        int n = mT + warpM * 16 + h * 8 + (l >> 2);
        size_t base = (size_t)b * NPIX * KCAT + (size_t)n * KCAT;
        #pragma unroll
        for (int ni = 0; ni < 8; ni++) {
            int cl = ni * 8 + 2 * (l & 3);
            float v0 = acc[ni][h * 2 + 0] + bias[cl];
            float v1 = acc[ni][h * 2 + 1] + bias[cl + 1];
            __nv_bfloat16 h0 = __float2bfloat16(v0);
            __nv_bfloat16 h1 = __float2bfloat16(v1);
            __nv_bfloat162 hi2; hi2.x = h0; hi2.y = h1;
            __nv_bfloat162 lo2;
            lo2.x = __float2bfloat16(v0 - __bfloat162float(h0));
            lo2.y = __float2bfloat16(v1 - __bfloat162float(h1));
            if (warpN == 0) {
                *(__nv_bfloat162*)&dst[base + cl]       = hi2;
                *(__nv_bfloat162*)&dst[base + 64 + cl]  = lo2;
                *(__nv_bfloat162*)&dst[base + 128 + cl] = hi2;
            } else {
                *(__nv_bfloat162*)&dst[base + cl]       = hi2;
                *(__nv_bfloat162*)&dst[base + 64 + cl]  = hi2;
                *(__nv_bfloat162*)&dst[base + 128 + cl] = lo2;
            }
        }
    }
}

// ---------------- v-proj (BK=64, 3-stage) -----------------------------------
__global__ __launch_bounds__(256) void vproj_mma(const float* __restrict__ bv)
{
    constexpr int K = CH, KI = K / 64;   // 8
    constexpr int STG = 2 * 128 * 128;   // 32KB
    extern __shared__ __align__(1024) char smem[];
    uint32_t sb = smem_u32(smem);

    int tid = threadIdx.x, wid = tid >> 5, l = tid & 31;
    int warpM = wid >> 1, warpN = wid & 1;
    int b = blockIdx.z;
    int nT = blockIdx.x * 128;
    int mT = blockIdx.y * 128;

    const __nv_bfloat16* Ag = g_wv_bf + (size_t)mT * CH;
    const __nv_bfloat16* Bg = g_xt_hi + (size_t)b * NPIX * CH + (size_t)nT * CH;

    auto load_stage = [&](int s, int kt) {
        uint32_t aB = sb + s * STG, bB = aB + 16384;
        int k0 = kt * 64;
        #pragma unroll
        for (int u = 0; u < 4; u++) {
            int idx = tid + u * 256, r = idx >> 3, c = idx & 7;
            cp16(aB + sw8(r, c), Ag + (size_t)r * K + k0 + c * 8);
        }
        #pragma unroll
        for (int u = 0; u < 4; u++) {
            int idx = tid + u * 256, r = idx >> 3, c = idx & 7;
            cp16(bB + sw8(r, c), Bg + (size_t)r * K + k0 + c * 8);
        }
        CP_COMMIT();
    };

    float acc[2][8][4];
    #pragma unroll
    for (int i = 0; i < 2; i++)
        #pragma unroll
        for (int j = 0; j < 8; j++)
            #pragma unroll
            for (int q = 0; q < 4; q++) acc[i][j][q] = 0.f;

    load_stage(0, 0); load_stage(1, 1);

    for (int it = 0; it < KI; it++) {
        int s = it % 3;
        if (it + 1 < KI) CP_WAIT(1); else CP_WAIT(0);
        __syncthreads();
        if (it + 2 < KI) load_stage((it + 2) % 3, it + 2);

        uint32_t aP = sb + s * STG, bP = aP + 16384;
        #pragma unroll
        for (int ks = 0; ks < 4; ks++) {
            uint32_t af[2][4];
            #pragma unroll
            for (int mi = 0; mi < 2; mi++) {
                uint32_t row = warpM * 32 + mi * 16 + (l & 15);
                uint32_t ch  = ks * 2 + (l >> 4);
                ldm_x4(af[mi], aP + sw8(row, ch));
            }
            uint32_t bfm[4][4];
            #pragma unroll
            for (int nb = 0; nb < 4; nb++) {
                uint32_t row = warpN * 64 + nb * 16 + ((l >> 4) << 3) + (l & 7);
                uint32_t ch  = ks * 2 + ((l >> 3) & 1);
                ldm_x4(bfm[nb], bP + sw8(row, ch));
            }
            #pragma unroll
            for (int mi = 0; mi < 2; mi++)
                #pragma unroll
                for (int ni = 0; ni < 8; ni++)
                    mma_bf16(acc[mi][ni], af[mi], &bfm[ni >> 1][(ni & 1) * 2]);
        }
        __syncthreads();
    }

    #pragma unroll
    for (int mi = 0; mi < 2; mi++)
        #pragma unroll
        for (int h = 0; h < 2; h++) {
            int m = mT + warpM * 32 + mi * 16 + h * 8 + (l >> 2);
            float bb = bv[m];
            #pragma unroll
            for (int ni = 0; ni < 8; ni++) {
                int n = nT + warpN * 64 + ni * 8 + 2 * (l & 3);
                __nv_bfloat162 pk = __floats2bfloat162_rn(acc[mi][ni][h * 2 + 0] + bb,
                                                          acc[mi][ni][h * 2 + 1] + bb);
                *(__nv_bfloat162*)&g_v_bf[(size_t)b * CH * NPIX +
                                          (size_t)m * NPIX + n] = pk;
            }
        }
}

// ---------------- energy (BK=64, 3-stage): P'[n,m] = exp(qcat·kcat) --------
__global__ __launch_bounds__(256) void energy_mma()
{
    constexpr int K = KCAT, KI = K / 64;   // 3
    constexpr int STG = 2 * 128 * 128;
    extern __shared__ __align__(1024) char smem[];
    uint32_t sb = smem_u32(smem);

    int tid = threadIdx.x, wid = tid >> 5, l = tid & 31;
    int warpM = wid >> 1, warpN = wid & 1;
    int b = blockIdx.z;
    int nT = blockIdx.x * 128;
    int mT = blockIdx.y * 128;

    const __nv_bfloat16* Ag = g_qcat + (size_t)b * NPIX * KCAT + (size_t)mT * KCAT;
    const __nv_bfloat16* Bg = g_kcat + (size_t)b * NPIX * KCAT + (size_t)nT * KCAT;

    auto load_stage = [&](int s, int kt) {
        uint32_t aB = sb + s * STG, bB = aB + 16384;
        int k0 = kt * 64;
        #pragma unroll
        for (int u = 0; u < 4; u++) {
            int idx = tid + u * 256, r = idx >> 3, c = idx & 7;
            cp16(aB + sw8(r, c), Ag + (size_t)r * K + k0 + c * 8);
        }
        #pragma unroll
        for (int u = 0; u < 4; u++) {
            int idx = tid + u * 256, r = idx >> 3, c = idx & 7;
            cp16(bB + sw8(r, c), Bg + (size_t)r * K + k0 + c * 8);
        }
        CP_COMMIT();
    };

    float acc[2][8][4];
    #pragma unroll
    for (int i = 0; i < 2; i++)
        #pragma unroll
        for (int j = 0; j < 8; j++)
            #pragma unroll
            for (int q = 0; q < 4; q++) acc[i][j][q] = 0.f;

    load_stage(0, 0); load_stage(1, 1);

    for (int it = 0; it < KI; it++) {
        int s = it % 3;
        if (it + 1 < KI) CP_WAIT(1); else CP_WAIT(0);
        __syncthreads();
        if (it + 2 < KI) load_stage((it + 2) % 3, it + 2);

        uint32_t aP = sb + s * STG, bP = aP + 16384;
        #pragma unroll
        for (int ks = 0; ks < 4; ks++) {
            uint32_t af[2][4];
            #pragma unroll
            for (int mi = 0; mi < 2; mi++) {
                uint32_t row = warpM * 32 + mi * 16 + (l & 15);
                uint32_t ch  = ks * 2 + (l >> 4);
                ldm_x4(af[mi], aP + sw8(row, ch));
            }
            uint32_t bfm[4][4];
            #pragma unroll
            for (int nb = 0; nb < 4; nb++) {
                uint32_t row = warpN * 64 + nb * 16 + ((l >> 4) << 3) + (l & 7);
                uint32_t ch  = ks * 2 + ((l >> 3) & 1);
                ldm_x4(bfm[nb], bP + sw8(row, ch));
            }
            #pragma unroll
            for (int mi = 0; mi < 2; mi++)
                #pragma unroll
                for (int ni = 0; ni < 8; ni++)
                    mma_bf16(acc[mi][ni], af[mi], &bfm[ni >> 1][(ni & 1) * 2]);
        }
        __syncthreads();
    }

    #pragma unroll
    for (int mi = 0; mi < 2; mi++)
        #pragma unroll
        for (int h = 0; h < 2; h++) {
            int n = mT + warpM * 32 + mi * 16 + h * 8 + (l >> 2);
            float rp = 0.f;
            #pragma unroll
            for (int ni = 0; ni < 8; ni++) {
                int m = nT + warpN * 64 + ni * 8 + 2 * (l & 3);
                float p0 = __expf(acc[mi][ni][h * 2 + 0]);
                float p1 = __expf(acc[mi][ni][h * 2 + 1]);
                rp += p0 + p1;
                *(__nv_bfloat162*)&g_attn_bf[(size_t)b * NPIX * NPIX +
                                             (size_t)n * NPIX + m] =
                    __floats2bfloat162_rn(p0, p1);
            }
            rp += __shfl_xor_sync(0xffffffffu, rp, 1);
            rp += __shfl_xor_sync(0xffffffffu, rp, 2);
            if ((l & 3) == 0)
                atomicAdd(&g_rowsum[b * NPIX + n], rp);
        }
}

// ---------------- out GEMM (BK=64, 4-stage): y = g*(v·P'^T)/rs + x ---------
static constexpr int OUT_STG = 256 * 128 + 128 * 128;  // A 32KB + B 16KB
__global__ __launch_bounds__(256, 1) void out_gemm(const float* __restrict__ xin,
                                                   const float* __restrict__ gamma,
                                                   float* __restrict__ y)
{
    constexpr int K = NPIX, KI = K / 64;   // 64
    extern __shared__ __align__(1024) char smem[];
    __shared__ float s_inv[128];
    uint32_t sb = smem_u32(smem);

    int tid = threadIdx.x, wid = tid >> 5, l = tid & 31;
    int warpM = wid >> 1, warpN = wid & 1;
    int b = blockIdx.z;
    int nT = blockIdx.x * 128;   // i tile
    int mT = blockIdx.y * 256;   // c tile

    if (tid < 128)
        s_inv[tid] = __fdividef(gamma[0], g_rowsum[b * NPIX + nT + tid]);

    const __nv_bfloat16* Ag = g_v_bf    + (size_t)b * CH * NPIX   + (size_t)mT * NPIX;
    const __nv_bfloat16* Bg = g_attn_bf + (size_t)b * NPIX * NPIX + (size_t)nT * NPIX;

    auto load_stage = [&](int s, int kt) {
        uint32_t aB = sb + s * OUT_STG, bB = aB + 32768;
        int k0 = kt * 64;
        #pragma unroll
        for (int u = 0; u < 8; u++) {
            int idx = tid + u * 256, r = idx >> 3, c = idx & 7;
            cp16(aB + sw8(r, c), Ag + (size_t)r * K + k0 + c * 8);
        }
        #pragma unroll
        for (int u = 0; u < 4; u++) {
            int idx = tid + u * 256, r = idx >> 3, c = idx & 7;
            cp16(bB + sw8(r, c), Bg + (size_t)r * K + k0 + c * 8);
        }
        CP_COMMIT();
    };

    float acc[4][8][4];
    #pragma unroll
    for (int i = 0; i < 4; i++)
        #pragma unroll
        for (int j = 0; j < 8; j++)
            #pragma unroll
            for (int q = 0; q < 4; q++) acc[i][j][q] = 0.f;

    load_stage(0, 0); load_stage(1, 1); load_stage(2, 2);

    for (int it = 0; it < KI; it++) {
        int s = it & 3;
        if (it + 1 < KI) CP_WAIT(2); else CP_WAIT(0);
        __syncthreads();
        if (it + 3 < KI) load_stage((it + 3) & 3, it + 3);

        uint32_t aP = sb + s * OUT_STG, bP = aP + 32768;
        #pragma unroll
        for (int ks = 0; ks < 4; ks++) {
            uint32_t af[4][4];
            #pragma unroll
            for (int mi = 0; mi < 4; mi++) {
                uint32_t row = warpM * 64 + mi * 16 + (l & 15);
                uint32_t ch  = ks * 2 + (l >> 4);
                ldm_x4(af[mi], aP + sw8(row, ch));
            }
            uint32_t bfm[4][4];
            #pragma unroll
            for (int nb = 0; nb < 4; nb++) {
                uint32_t row = warpN * 64 + nb * 16 + ((l >> 4) << 3) + (l & 7);
                uint32_t ch  = ks * 2 + ((l >> 3) & 1);
                ldm_x4(bfm[nb], bP + sw8(row, ch));
            }
            #pragma unroll
            for (int mi = 0; mi < 4; mi++)
                #pragma unroll
                for (int ni = 0; ni < 8; ni++)
                    mma_bf16(acc[mi][ni], af[mi], &bfm[ni >> 1][(ni & 1) * 2]);
        }
        __syncthreads();
    }

    #pragma unroll
    for (int mi = 0; mi < 4; mi++)
        #pragma unroll
        for (int h = 0; h < 2; h++) {
            int m = mT + warpM * 64 + mi * 16 + h * 8 + (l >> 2);
            #pragma unroll
            for (int ni = 0; ni < 8; ni++) {
                int nl = warpN * 64 + ni * 8 + 2 * (l & 3);
                int n = nT + nl;
                float i0 = s_inv[nl];
                float i1 = s_inv[nl + 1];
                size_t idx = (size_t)b * CH * NPIX + (size_t)m * NPIX + n;
                float2 xv = *(const float2*)(xin + idx);
                float2 o  = make_float2(fmaf(i0, acc[mi][ni][h * 2 + 0], xv.x),
                                        fmaf(i1, acc[mi][ni][h * 2 + 1], xv.y));
                *(float2*)(y + idx) = o;
            }
        }
}

// ---------------------------------------------------------------------------
extern "C" void kernel_launch(void* const* d_in, const int* in_sizes, int n_in,
                              void* d_out, int out_size)
{
    const float* x     = (const float*)d_in[0];
    const float* Wq    = (const float*)d_in[1];
    const float* bq    = (const float*)d_in[2];
    const float* Wk    = (const float*)d_in[3];
    const float* bk    = (const float*)d_in[4];
    const float* Wv    = (const float*)d_in[5];
    const float* bv    = (const float*)d_in[6];
    const float* gamma = (const float*)d_in[7];
    float* y = (float*)d_out;

    constexpr int PQK_SMEM = 3 * (64 * 128 + 128 * 128);   // 72 KB
    constexpr int VE_SMEM  = 3 * (2 * 128 * 128);          // 96 KB
    constexpr int OUT_SMEM = 4 * OUT_STG;                  // 192 KB

    cudaFuncSetAttribute(projqk_mma, cudaFuncAttributeMaxDynamicSharedMemorySize, PQK_SMEM);
    cudaFuncSetAttribute(vproj_mma,  cudaFuncAttributeMaxDynamicSharedMemorySize, VE_SMEM);
    cudaFuncSetAttribute(energy_mma, cudaFuncAttributeMaxDynamicSharedMemorySize, VE_SMEM);
    cudaFuncSetAttribute(out_gemm,   cudaFuncAttributeMaxDynamicSharedMemorySize, OUT_SMEM);

    prep_w<<<(CH * CH + 2 * CQD * CH + 255) / 256, 256>>>(Wv, Wq, Wk);
    transpose_x<<<dim3(NPIX / 32, CH / 32, BATCH), 256>>>(x);
    projqk_mma<<<dim3(1, NPIX / 64, BATCH), 256, PQK_SMEM>>>(bq, bk);
    vproj_mma<<<dim3(NPIX / 128, CH / 128, BATCH), 256, VE_SMEM>>>(bv);
    energy_mma<<<dim3(NPIX / 128, NPIX / 128, BATCH), 256, VE_SMEM>>>();
    out_gemm<<<dim3(NPIX / 128, CH / 256, BATCH), 256, OUT_SMEM>>>(x, gamma, y);
}

// round 17
// speedup vs baseline: 1.1077x; 1.0451x over previous
#include <cuda_runtime.h>
#include <cuda_bf16.h>
#include <math.h>
#include <stdint.h>

#define BATCH 8
#define CH    512
#define CQD   64
#define NPIX  4096
#define KCAT  192   // [hi|lo|hi]·[hi|hi|lo] concat-K split-bf16 energy

// ---------------- scratch (device globals) ---------------------------------
__device__ __align__(256) __nv_bfloat16 g_attn_bf[(size_t)BATCH * NPIX * NPIX]; // 256MB exp(E)
__device__ __align__(256) __nv_bfloat16 g_xt_hi[(size_t)BATCH * NPIX * CH]; // 32 MB
__device__ __align__(256) __nv_bfloat16 g_xt_lo[(size_t)BATCH * NPIX * CH]; // 32 MB
__device__ __align__(256) __nv_bfloat16 g_v_bf[(size_t)BATCH * CH * NPIX];  // 32 MB
__device__ __align__(256) __nv_bfloat16 g_qcat[(size_t)BATCH * NPIX * KCAT];// 12 MB
__device__ __align__(256) __nv_bfloat16 g_kcat[(size_t)BATCH * NPIX * KCAT];// 12 MB
__device__ __align__(256) __nv_bfloat16 g_wv_bf[CH * CH];
__device__ __align__(256) __nv_bfloat16 g_wqk_hi[2 * CQD * CH];  // rows 0-63 Wq, 64-127 Wk
__device__ __align__(256) __nv_bfloat16 g_wqk_lo[2 * CQD * CH];
__device__ __align__(256) float g_rowsum[BATCH * NPIX];

// ---------------- helpers ---------------------------------------------------
__device__ __forceinline__ uint32_t smem_u32(const void* p) {
    uint32_t a;
    asm("{ .reg .u64 t; cvta.to.shared.u64 t, %1; cvt.u32.u64 %0, t; }" : "=r"(a) : "l"(p));
    return a;
}
__device__ __forceinline__ void cp16(uint32_t dst, const void* src) {
    asm volatile("cp.async.cg.shared.global [%0], [%1], 16;" :: "r"(dst), "l"(src));
}
#define CP_COMMIT() asm volatile("cp.async.commit_group;" ::: "memory")
#define CP_WAIT(n)  asm volatile("cp.async.wait_group %0;" :: "n"(n) : "memory")

__device__ __forceinline__ void ldm_x4(uint32_t* r, uint32_t addr) {
    asm volatile("ldmatrix.sync.aligned.m8n8.x4.shared.b16 {%0,%1,%2,%3}, [%4];"
                 : "=r"(r[0]), "=r"(r[1]), "=r"(r[2]), "=r"(r[3]) : "r"(addr));
}
__device__ __forceinline__ void mma_bf16(float* c, const uint32_t* a, const uint32_t* b) {
    asm volatile(
        "mma.sync.aligned.m16n8k16.row.col.f32.bf16.bf16.f32 "
        "{%0,%1,%2,%3}, {%4,%5,%6,%7}, {%8,%9}, {%0,%1,%2,%3};"
        : "+f"(c[0]), "+f"(c[1]), "+f"(c[2]), "+f"(c[3])
        : "r"(a[0]), "r"(a[1]), "r"(a[2]), "r"(a[3]), "r"(b[0]), "r"(b[1]));
}
// SW128 swizzle for 128B rows (BK=64 bf16): chunk 0..7 within row
__device__ __forceinline__ uint32_t sw8(uint32_t row, uint32_t ch) {
    return row * 128u + ((ch ^ (row & 7u)) << 4);
}

// ---------------- weight prep + rowsum zero ---------------------------------
__global__ __launch_bounds__(256) void prep_w(const float* __restrict__ Wv,
                                              const float* __restrict__ Wq,
                                              const float* __restrict__ Wk)
{
    int i = blockIdx.x * 256 + threadIdx.x;
    if (i < BATCH * NPIX) g_rowsum[i] = 0.f;
    if (i < CH * CH) {
        g_wv_bf[i] = __float2bfloat16(Wv[i]);
    } else {
        int j = i - CH * CH;
        if (j < 2 * CQD * CH) {
            float v = (j < CQD * CH) ? Wq[j] : Wk[j - CQD * CH];
            __nv_bfloat16 hi = __float2bfloat16(v);
            g_wqk_hi[j] = hi;
            g_wqk_lo[j] = __float2bfloat16(v - __bfloat162float(hi));
        }
    }
}

// ---------------- x transpose -> bf16 hi/lo [b][n][k] -----------------------
__global__ __launch_bounds__(256) void transpose_x(const float* __restrict__ x)
{
    __shared__ float t[32][33];
    int b = blockIdx.z;
    int n0 = blockIdx.x * 32, k0 = blockIdx.y * 32;
    int tx = threadIdx.x & 31, ty = threadIdx.x >> 5;
    #pragma unroll
    for (int i = 0; i < 32; i += 8)
        t[ty + i][tx] = x[(size_t)b * CH * NPIX + (size_t)(k0 + ty + i) * NPIX + n0 + tx];
    __syncthreads();
    #pragma unroll
    for (int i = 0; i < 32; i += 8) {
        float v = t[tx][ty + i];
        __nv_bfloat16 hi = __float2bfloat16(v);
        size_t idx = (size_t)b * NPIX * CH + (size_t)(n0 + ty + i) * CH + k0 + tx;
        g_xt_hi[idx] = hi;
        g_xt_lo[idx] = __float2bfloat16(v - __bfloat162float(hi));
    }
}

// ---------------- q/k projection via split-bf16 MMA (BK=64, 3-stage) --------
__global__ __launch_bounds__(256) void projqk_mma(const float* __restrict__ bq,
                                                  const float* __restrict__ bk)
{
    constexpr int K = CH;
    constexpr int TOT_IT = 24;                     // 3 passes x 8
    constexpr int STG = 64 * 128 + 128 * 128;      // A 8KB + B 16KB
    extern __shared__ __align__(1024) char smem[];
    uint32_t sb = smem_u32(smem);

    int tid = threadIdx.x, wid = tid >> 5, l = tid & 31;
    int warpM = wid & 3, warpN = wid >> 2;
    int b = blockIdx.z;
    int mT = blockIdx.y * 64;

    const __nv_bfloat16* xh = g_xt_hi + (size_t)b * NPIX * CH + (size_t)mT * CH;
    const __nv_bfloat16* xl = g_xt_lo + (size_t)b * NPIX * CH + (size_t)mT * CH;

    auto load_stage = [&](int s, int gIt) {
        int pass = gIt >> 3;
        int k0 = (gIt & 7) * 64;
        const __nv_bfloat16* Ag = (pass == 1) ? xl : xh;
        const __nv_bfloat16* Bg = (pass == 2) ? g_wqk_lo : g_wqk_hi;
        uint32_t aB = sb + s * STG, bB = aB + 8192;
        #pragma unroll
        for (int u = 0; u < 2; u++) {
            int idx = tid + u * 256, r = idx >> 3, c = idx & 7;
            cp16(aB + sw8(r, c), Ag + (size_t)r * K + k0 + c * 8);
        }
        #pragma unroll
        for (int u = 0; u < 4; u++) {
            int idx = tid + u * 256, r = idx >> 3, c = idx & 7;
            cp16(bB + sw8(r, c), Bg + (size_t)r * K + k0 + c * 8);
        }
        CP_COMMIT();
    };

    // one ks-group of compute (ldmatrix + mma)
    auto compute_ks = [&](uint32_t aP, uint32_t bP, int ks, float (*acc)[4]) {
        uint32_t af[4];
        { uint32_t row = warpM * 16 + (l & 15), ch = ks * 2 + (l >> 4);
          ldm_x4(af, aP + sw8(row, ch)); }
        uint32_t bfm[4][4];
        #pragma unroll
        for (int nb = 0; nb < 4; nb++) {
            uint32_t row = warpN * 64 + nb * 16 + ((l >> 4) << 3) + (l & 7);
            uint32_t ch  = ks * 2 + ((l >> 3) & 1);
            ldm_x4(bfm[nb], bP + sw8(row, ch));
        }
        #pragma unroll
        for (int ni = 0; ni < 8; ni++)
            mma_bf16(acc[ni], af, &bfm[ni >> 1][(ni & 1) * 2]);
    };

    float acc[8][4];
    #pragma unroll
    for (int j = 0; j < 8; j++)
        #pragma unroll
        for (int q = 0; q < 4; q++) acc[j][q] = 0.f;

    load_stage(0, 0); load_stage(1, 1);

    for (int it = 0; it < TOT_IT; it++) {
        int s = it % 3;
        if (it + 1 < TOT_IT) CP_WAIT(1); else CP_WAIT(0);
        __syncthreads();

        uint32_t aP = sb + s * STG, bP = aP + 8192;
        compute_ks(aP, bP, 0, acc);                       // ks=0 first
        if (it + 2 < TOT_IT) load_stage((it + 2) % 3, it + 2);  // prefetch after
        #pragma unroll
        for (int ks = 1; ks < 4; ks++)
            compute_ks(aP, bP, ks, acc);
        __syncthreads();
    }

    const float* bias = (warpN == 0) ? bq : bk;
    __nv_bfloat16* dst = (warpN == 0) ? g_qcat : g_kcat;
    #pragma unroll
    for (int h = 0; h < 2; h++) {
        int n = mT + warpM * 16 + h * 8 + (l >> 2);
        size_t base = (size_t)b * NPIX * KCAT + (size_t)n * KCAT;
        #pragma unroll
        for (int ni = 0; ni < 8; ni++) {
            int cl = ni * 8 + 2 * (l & 3);
            float v0 = acc[ni][h * 2 + 0] + bias[cl];
            float v1 = acc[ni][h * 2 + 1] + bias[cl + 1];
            __nv_bfloat16 h0 = __float2bfloat16(v0);
            __nv_bfloat16 h1 = __float2bfloat16(v1);
            __nv_bfloat162 hi2; hi2.x = h0; hi2.y = h1;
            __nv_bfloat162 lo2;
            lo2.x = __float2bfloat16(v0 - __bfloat162float(h0));
            lo2.y = __float2bfloat16(v1 - __bfloat162float(h1));
            if (warpN == 0) {
                *(__nv_bfloat162*)&dst[base + cl]       = hi2;
                *(__nv_bfloat162*)&dst[base + 64 + cl]  = lo2;
                *(__nv_bfloat162*)&dst[base + 128 + cl] = hi2;
            } else {
                *(__nv_bfloat162*)&dst[base + cl]       = hi2;
                *(__nv_bfloat162*)&dst[base + 64 + cl]  = hi2;
                *(__nv_bfloat162*)&dst[base + 128 + cl] = lo2;
            }
        }
    }
}

// ---------------- v-proj (BK=64, 3-stage) -----------------------------------
__global__ __launch_bounds__(256) void vproj_mma(const float* __restrict__ bv)
{
    constexpr int K = CH, KI = K / 64;   // 8
    constexpr int STG = 2 * 128 * 128;   // 32KB
    extern __shared__ __align__(1024) char smem[];
    uint32_t sb = smem_u32(smem);

    int tid = threadIdx.x, wid = tid >> 5, l = tid & 31;
    int warpM = wid >> 1, warpN = wid & 1;
    int b = blockIdx.z;
    int nT = blockIdx.x * 128;
    int mT = blockIdx.y * 128;

    const __nv_bfloat16* Ag = g_wv_bf + (size_t)mT * CH;
    const __nv_bfloat16* Bg = g_xt_hi + (size_t)b * NPIX * CH + (size_t)nT * CH;

    auto load_stage = [&](int s, int kt) {
        uint32_t aB = sb + s * STG, bB = aB + 16384;
        int k0 = kt * 64;
        #pragma unroll
        for (int u = 0; u < 4; u++) {
            int idx = tid + u * 256, r = idx >> 3, c = idx & 7;
            cp16(aB + sw8(r, c), Ag + (size_t)r * K + k0 + c * 8);
        }
        #pragma unroll
        for (int u = 0; u < 4; u++) {
            int idx = tid + u * 256, r = idx >> 3, c = idx & 7;
            cp16(bB + sw8(r, c), Bg + (size_t)r * K + k0 + c * 8);
        }
        CP_COMMIT();
    };

    auto compute_ks = [&](uint32_t aP, uint32_t bP, int ks, float (*acc)[8][4]) {
        uint32_t af[2][4];
        #pragma unroll
        for (int mi = 0; mi < 2; mi++) {
            uint32_t row = warpM * 32 + mi * 16 + (l & 15);
            uint32_t ch  = ks * 2 + (l >> 4);
            ldm_x4(af[mi], aP + sw8(row, ch));
        }
        uint32_t bfm[4][4];
        #pragma unroll
        for (int nb = 0; nb < 4; nb++) {
            uint32_t row = warpN * 64 + nb * 16 + ((l >> 4) << 3) + (l & 7);
            uint32_t ch  = ks * 2 + ((l >> 3) & 1);
            ldm_x4(bfm[nb], bP + sw8(row, ch));
        }
        #pragma unroll
        for (int mi = 0; mi < 2; mi++)
            #pragma unroll
            for (int ni = 0; ni < 8; ni++)
                mma_bf16(acc[mi][ni], af[mi], &bfm[ni >> 1][(ni & 1) * 2]);
    };

    float acc[2][8][4];
    #pragma unroll
    for (int i = 0; i < 2; i++)
        #pragma unroll
        for (int j = 0; j < 8; j++)
            #pragma unroll
            for (int q = 0; q < 4; q++) acc[i][j][q] = 0.f;

    load_stage(0, 0); load_stage(1, 1);

    for (int it = 0; it < KI; it++) {
        int s = it % 3;
        if (it + 1 < KI) CP_WAIT(1); else CP_WAIT(0);
        __syncthreads();

        uint32_t aP = sb + s * STG, bP = aP + 16384;
        compute_ks(aP, bP, 0, acc);
        if (it + 2 < KI) load_stage((it + 2) % 3, it + 2);
        #pragma unroll
        for (int ks = 1; ks < 4; ks++)
            compute_ks(aP, bP, ks, acc);
        __syncthreads();
    }

    #pragma unroll
    for (int mi = 0; mi < 2; mi++)
        #pragma unroll
        for (int h = 0; h < 2; h++) {
            int m = mT + warpM * 32 + mi * 16 + h * 8 + (l >> 2);
            float bb = bv[m];
            #pragma unroll
            for (int ni = 0; ni < 8; ni++) {
                int n = nT + warpN * 64 + ni * 8 + 2 * (l & 3);
                __nv_bfloat162 pk = __floats2bfloat162_rn(acc[mi][ni][h * 2 + 0] + bb,
                                                          acc[mi][ni][h * 2 + 1] + bb);
                *(__nv_bfloat162*)&g_v_bf[(size_t)b * CH * NPIX +
                                          (size_t)m * NPIX + n] = pk;
            }
        }
}

// ---------------- energy (BK=64, 3-stage): P'[n,m] = exp(qcat·kcat) --------
__global__ __launch_bounds__(256) void energy_mma()
{
    constexpr int K = KCAT, KI = K / 64;   // 3
    constexpr int STG = 2 * 128 * 128;
    extern __shared__ __align__(1024) char smem[];
    uint32_t sb = smem_u32(smem);

    int tid = threadIdx.x, wid = tid >> 5, l = tid & 31;
    int warpM = wid >> 1, warpN = wid & 1;
    int b = blockIdx.z;
    int nT = blockIdx.x * 128;
    int mT = blockIdx.y * 128;

    const __nv_bfloat16* Ag = g_qcat + (size_t)b * NPIX * KCAT + (size_t)mT * KCAT;
    const __nv_bfloat16* Bg = g_kcat + (size_t)b * NPIX * KCAT + (size_t)nT * KCAT;

    auto load_stage = [&](int s, int kt) {
        uint32_t aB = sb + s * STG, bB = aB + 16384;
        int k0 = kt * 64;
        #pragma unroll
        for (int u = 0; u < 4; u++) {
            int idx = tid + u * 256, r = idx >> 3, c = idx & 7;
            cp16(aB + sw8(r, c), Ag + (size_t)r * K + k0 + c * 8);
        }
        #pragma unroll
        for (int u = 0; u < 4; u++) {
            int idx = tid + u * 256, r = idx >> 3, c = idx & 7;
            cp16(bB + sw8(r, c), Bg + (size_t)r * K + k0 + c * 8);
        }
        CP_COMMIT();
    };

    auto compute_ks = [&](uint32_t aP, uint32_t bP, int ks, float (*acc)[8][4]) {
        uint32_t af[2][4];
        #pragma unroll
        for (int mi = 0; mi < 2; mi++) {
            uint32_t row = warpM * 32 + mi * 16 + (l & 15);
            uint32_t ch  = ks * 2 + (l >> 4);
            ldm_x4(af[mi], aP + sw8(row, ch));
        }
        uint32_t bfm[4][4];
        #pragma unroll
        for (int nb = 0; nb < 4; nb++) {
            uint32_t row = warpN * 64 + nb * 16 + ((l >> 4) << 3) + (l & 7);
            uint32_t ch  = ks * 2 + ((l >> 3) & 1);
            ldm_x4(bfm[nb], bP + sw8(row, ch));
        }
        #pragma unroll
        for (int mi = 0; mi < 2; mi++)
            #pragma unroll
            for (int ni = 0; ni < 8; ni++)
                mma_bf16(acc[mi][ni], af[mi], &bfm[ni >> 1][(ni & 1) * 2]);
    };

    float acc[2][8][4];
    #pragma unroll
    for (int i = 0; i < 2; i++)
        #pragma unroll
        for (int j = 0; j < 8; j++)
            #pragma unroll
            for (int q = 0; q < 4; q++) acc[i][j][q] = 0.f;

    load_stage(0, 0); load_stage(1, 1);

    for (int it = 0; it < KI; it++) {
        int s = it % 3;
        if (it + 1 < KI) CP_WAIT(1); else CP_WAIT(0);
        __syncthreads();

        uint32_t aP = sb + s * STG, bP = aP + 16384;
        compute_ks(aP, bP, 0, acc);
        if (it + 2 < KI) load_stage((it + 2) % 3, it + 2);
        #pragma unroll
        for (int ks = 1; ks < 4; ks++)
            compute_ks(aP, bP, ks, acc);
        __syncthreads();
    }

    #pragma unroll
    for (int mi = 0; mi < 2; mi++)
        #pragma unroll
        for (int h = 0; h < 2; h++) {
            int n = mT + warpM * 32 + mi * 16 + h * 8 + (l >> 2);
            float rp = 0.f;
            #pragma unroll
            for (int ni = 0; ni < 8; ni++) {
                int m = nT + warpN * 64 + ni * 8 + 2 * (l & 3);
                float p0 = __expf(acc[mi][ni][h * 2 + 0]);
                float p1 = __expf(acc[mi][ni][h * 2 + 1]);
                rp += p0 + p1;
                *(__nv_bfloat162*)&g_attn_bf[(size_t)b * NPIX * NPIX +
                                             (size_t)n * NPIX + m] =
                    __floats2bfloat162_rn(p0, p1);
            }
            rp += __shfl_xor_sync(0xffffffffu, rp, 1);
            rp += __shfl_xor_sync(0xffffffffu, rp, 2);
            if ((l & 3) == 0)
                atomicAdd(&g_rowsum[b * NPIX + n], rp);
        }
}

// ---------------- out GEMM (BK=64, 4-stage): y = g*(v·P'^T)/rs + x ---------
static constexpr int OUT_STG = 256 * 128 + 128 * 128;  // A 32KB + B 16KB
__global__ __launch_bounds__(256, 1) void out_gemm(const float* __restrict__ xin,
                                                   const float* __restrict__ gamma,
                                                   float* __restrict__ y)
{
    constexpr int K = NPIX, KI = K / 64;   // 64
    extern __shared__ __align__(1024) char smem[];
    __shared__ float s_inv[128];
    uint32_t sb = smem_u32(smem);

    int tid = threadIdx.x, wid = tid >> 5, l = tid & 31;
    int warpM = wid >> 1, warpN = wid & 1;
    int b = blockIdx.z;
    int nT = blockIdx.x * 128;   // i tile
    int mT = blockIdx.y * 256;   // c tile

    if (tid < 128)
        s_inv[tid] = __fdividef(gamma[0], g_rowsum[b * NPIX + nT + tid]);

    const __nv_bfloat16* Ag = g_v_bf    + (size_t)b * CH * NPIX   + (size_t)mT * NPIX;
    const __nv_bfloat16* Bg = g_attn_bf + (size_t)b * NPIX * NPIX + (size_t)nT * NPIX;

    auto load_stage = [&](int s, int kt) {
        uint32_t aB = sb + s * OUT_STG, bB = aB + 32768;
        int k0 = kt * 64;
        #pragma unroll
        for (int u = 0; u < 8; u++) {
            int idx = tid + u * 256, r = idx >> 3, c = idx & 7;
            cp16(aB + sw8(r, c), Ag + (size_t)r * K + k0 + c * 8);
        }
        #pragma unroll
        for (int u = 0; u < 4; u++) {
            int idx = tid + u * 256, r = idx >> 3, c = idx & 7;
            cp16(bB + sw8(r, c), Bg + (size_t)r * K + k0 + c * 8);
        }
        CP_COMMIT();
    };

    auto compute_ks = [&](uint32_t aP, uint32_t bP, int ks, float (*acc)[8][4]) {
        uint32_t af[4][4];
        #pragma unroll
        for (int mi = 0; mi < 4; mi++) {
            uint32_t row = warpM * 64 + mi * 16 + (l & 15);
            uint32_t ch  = ks * 2 + (l >> 4);
            ldm_x4(af[mi], aP + sw8(row, ch));
        }
        uint32_t bfm[4][4];
        #pragma unroll
        for (int nb = 0; nb < 4; nb++) {
            uint32_t row = warpN * 64 + nb * 16 + ((l >> 4) << 3) + (l & 7);
            uint32_t ch  = ks * 2 + ((l >> 3) & 1);
            ldm_x4(bfm[nb], bP + sw8(row, ch));
        }
        #pragma unroll
        for (int mi = 0; mi < 4; mi++)
            #pragma unroll
            for (int ni = 0; ni < 8; ni++)
                mma_bf16(acc[mi][ni], af[mi], &bfm[ni >> 1][(ni & 1) * 2]);
    };

    float acc[4][8][4];
    #pragma unroll
    for (int i = 0; i < 4; i++)
        #pragma unroll
        for (int j = 0; j < 8; j++)
            #pragma unroll
            for (int q = 0; q < 4; q++) acc[i][j][q] = 0.f;

    load_stage(0, 0); load_stage(1, 1); load_stage(2, 2);

    for (int it = 0; it < KI; it++) {
        int s = it & 3;
        if (it + 1 < KI) CP_WAIT(2); else CP_WAIT(0);
        __syncthreads();

        uint32_t aP = sb + s * OUT_STG, bP = aP + 32768;
        compute_ks(aP, bP, 0, acc);
        if (it + 3 < KI) load_stage((it + 3) & 3, it + 3);
        #pragma unroll
        for (int ks = 1; ks < 4; ks++)
            compute_ks(aP, bP, ks, acc);
        __syncthreads();
    }

    #pragma unroll
    for (int mi = 0; mi < 4; mi++)
        #pragma unroll
        for (int h = 0; h < 2; h++) {
            int m = mT + warpM * 64 + mi * 16 + h * 8 + (l >> 2);
            #pragma unroll
            for (int ni = 0; ni < 8; ni++) {
                int nl = warpN * 64 + ni * 8 + 2 * (l & 3);
                int n = nT + nl;
                float i0 = s_inv[nl];
                float i1 = s_inv[nl + 1];
                size_t idx = (size_t)b * CH * NPIX + (size_t)m * NPIX + n;
                float2 xv = *(const float2*)(xin + idx);
                float2 o  = make_float2(fmaf(i0, acc[mi][ni][h * 2 + 0], xv.x),
                                        fmaf(i1, acc[mi][ni][h * 2 + 1], xv.y));
                *(float2*)(y + idx) = o;
            }
        }
}

// ---------------------------------------------------------------------------
extern "C" void kernel_launch(void* const* d_in, const int* in_sizes, int n_in,
                              void* d_out, int out_size)
{
    const float* x     = (const float*)d_in[0];
    const float* Wq    = (const float*)d_in[1];
    const float* bq    = (const float*)d_in[2];
    const float* Wk    = (const float*)d_in[3];
    const float* bk    = (const float*)d_in[4];
    const float* Wv    = (const float*)d_in[5];
    const float* bv    = (const float*)d_in[6];
    const float* gamma = (const float*)d_in[7];
    float* y = (float*)d_out;

    constexpr int PQK_SMEM = 3 * (64 * 128 + 128 * 128);   // 72 KB
    constexpr int VE_SMEM  = 3 * (2 * 128 * 128);          // 96 KB
    constexpr int OUT_SMEM = 4 * OUT_STG;                  // 192 KB

    cudaFuncSetAttribute(projqk_mma, cudaFuncAttributeMaxDynamicSharedMemorySize, PQK_SMEM);
    cudaFuncSetAttribute(vproj_mma,  cudaFuncAttributeMaxDynamicSharedMemorySize, VE_SMEM);
    cudaFuncSetAttribute(energy_mma, cudaFuncAttributeMaxDynamicSharedMemorySize, VE_SMEM);
    cudaFuncSetAttribute(out_gemm,   cudaFuncAttributeMaxDynamicSharedMemorySize, OUT_SMEM);

    prep_w<<<(CH * CH + 2 * CQD * CH + 255) / 256, 256>>>(Wv, Wq, Wk);
    transpose_x<<<dim3(NPIX / 32, CH / 32, BATCH), 256>>>(x);
    projqk_mma<<<dim3(1, NPIX / 64, BATCH), 256, PQK_SMEM>>>(bq, bk);
    vproj_mma<<<dim3(NPIX / 128, CH / 128, BATCH), 256, VE_SMEM>>>(bv);
    energy_mma<<<dim3(NPIX / 128, NPIX / 128, BATCH), 256, VE_SMEM>>>();
    out_gemm<<<dim3(NPIX / 128, CH / 256, BATCH), 256, OUT_SMEM>>>(x, gamma, y);
}